// round 13
// baseline (speedup 1.0000x reference)
#include <cuda_runtime.h>
#include <cuda_fp16.h>

#define HDIM   64
#define NHEADS 4
#define QKDIM  256           // NHEADS * HDIM
#define N_SRC  50000
#define N_TGT  10000
#define N_E    250000
#define N_LBL  200000

#define PADK   72            // smem row stride in fp16 (144B): ldmatrix conflict-free
#define WSECT  (832 * 64)    // per (layer,edge_type) transposed weight block (elements)
#define NBS    391           // (N_SRC+127)/128
#define NBT    79            // (N_TGT+127)/128

// ---------------- scratch (static device memory; no allocations) ----------------
__device__ float g_xs_a[N_SRC * HDIM];
__device__ float g_xs_b[N_SRC * HDIM];
__device__ float g_xt_a[N_TGT * HDIM];
__device__ float g_xt_b[N_TGT * HDIM];

__device__ __align__(16) __half g_q_st[N_TGT * QKDIM];
__device__ __align__(16) __half g_k_ts[N_TGT * QKDIM];
__device__ __align__(16) __half g_v_ts[N_TGT * QKDIM];
__device__ __align__(16) __half g_q_ts[N_SRC * QKDIM];
__device__ __align__(16) __half g_k_st[N_SRC * QKDIM];
__device__ __align__(16) __half g_v_st[N_SRC * QKDIM];

__device__ float g_sc_st[N_E * NHEADS];
__device__ float g_sc_ts[N_E * NHEADS];
__device__ float g_d_st[N_TGT * NHEADS];
__device__ float g_d_ts[N_SRC * NHEADS];

// A operand: fp16. B: split-fp16 (hi + residual).
__device__ __align__(16) __half g_xsh[N_SRC * HDIM];
__device__ __align__(16) __half g_xth[N_TGT * HDIM];
__device__ __align__(16) __half g_wth[4 * WSECT];
__device__ __align__(16) __half g_wtl[4 * WSECT];

// ---------------- helpers ----------------
__device__ __forceinline__ void split2h(float v, __half& h, __half& l) {
    h = __float2half_rn(v);
    l = __float2half_rn(v - __half2float(h));
}
__device__ __forceinline__ unsigned su32(const void* p) {
    unsigned a;
    asm("{ .reg .u64 t; cvta.to.shared.u64 t, %1; cvt.u32.u64 %0, t; }" : "=r"(a) : "l"(p));
    return a;
}
__device__ __forceinline__ void ldsm4(unsigned& r0, unsigned& r1, unsigned& r2, unsigned& r3,
                                      unsigned addr) {
    asm volatile("ldmatrix.sync.aligned.m8n8.x4.shared.b16 {%0,%1,%2,%3}, [%4];"
                 : "=r"(r0), "=r"(r1), "=r"(r2), "=r"(r3) : "r"(addr));
}
__device__ __forceinline__ void mma16816h(float* d, const unsigned* a, unsigned b0, unsigned b1) {
    asm volatile("mma.sync.aligned.m16n8k16.row.col.f32.f16.f16.f32 "
                 "{%0,%1,%2,%3}, {%4,%5,%6,%7}, {%8,%9}, {%0,%1,%2,%3};"
                 : "+f"(d[0]), "+f"(d[1]), "+f"(d[2]), "+f"(d[3])
                 : "r"(a[0]), "r"(a[1]), "r"(a[2]), "r"(a[3]), "r"(b0), "r"(b1));
}
__device__ __forceinline__ float dot8h(uint4 qa, uint4 ka) {
    const __half2* qh = (const __half2*)&qa;
    const __half2* kh = (const __half2*)&ka;
    float dot = 0.0f;
    #pragma unroll
    for (int i = 0; i < 4; i++) {
        float2 a = __half22float2(qh[i]);
        float2 b = __half22float2(kh[i]);
        dot += a.x * b.x + a.y * b.y;
    }
    return dot;
}

// ---------------- small kernels ----------------
__global__ void zero2_kernel(float* __restrict__ a, int na, float* __restrict__ b, int nb) {
    int i = blockIdx.x * blockDim.x + threadIdx.x;
    if (i < na) { a[i] = 0.0f; return; }
    i -= na;
    if (i < nb) b[i] = 0.0f;
}

__global__ void gather_h2(const float* __restrict__ semb, const float* __restrict__ temb,
                          const int* __restrict__ sid, const int* __restrict__ tid) {
    int i = blockIdx.x * blockDim.x + threadIdx.x;
    if (i < N_SRC * HDIM) {
        int row = i >> 6, d = i & 63;
        g_xsh[i] = __float2half_rn(semb[(size_t)sid[row] * HDIM + d]);
    } else if (i < (N_SRC + N_TGT) * HDIM) {
        int j = i - N_SRC * HDIM;
        int row = j >> 6, d = j & 63;
        g_xth[j] = __float2half_rn(temb[(size_t)tid[row] * HDIM + d]);
    }
}

__global__ void relu_h2() {
    int i = blockIdx.x * blockDim.x + threadIdx.x;
    if (i < N_SRC * HDIM) {
        g_xsh[i] = __float2half_rn(fmaxf(g_xs_b[i], 0.0f));
    } else if (i < (N_SRC + N_TGT) * HDIM) {
        int j = i - N_SRC * HDIM;
        g_xth[j] = __float2half_rn(fmaxf(g_xt_b[j], 0.0f));
    }
}

__global__ void split_w(const float* __restrict__ Wq, const float* __restrict__ Wk,
                        const float* __restrict__ Wv, const float* __restrict__ Ws) {
    int i = blockIdx.x * blockDim.x + threadIdx.x;
    if (i >= 4 * WSECT) return;
    int le = i / WSECT, rem = i % WSECT;
    int n = rem >> 6, k = rem & 63;
    float v;
    if (n < 256)      v = Wq[(size_t)le * 64 * 256 + k * 256 + n];
    else if (n < 512) v = Wk[(size_t)le * 64 * 256 + k * 256 + (n - 256)];
    else if (n < 768) v = Wv[(size_t)le * 64 * 256 + k * 256 + (n - 512)];
    else              v = Ws[(size_t)le * 64 * 64 + k * 64 + (n - 768)];
    split2h(v, g_wth[i], g_wtl[i]);
}

// ---------------- fused projection: src+tgt sides, 13 slots over 3 sections -----
// grid = (NBS + NBT, 3). Section 0: slots 0-3, 1: 4-7, 2: 8-12.
// slot>>2 = group: 0..2 -> fp16 q/k/v-type outputs, 3 -> fp32 skip.
__global__ void __launch_bounds__(256) proj_all(
    int l, const float* __restrict__ bq, const float* __restrict__ bk,
    const float* __restrict__ bv, const float* __restrict__ bs) {
    extern __shared__ __half sm[];
    __half* Ah = sm;                           // [128][PADK]
    __half* Bh = Ah + 128 * PADK;              // [64][PADK]
    __half* Bl = Bh + 64 * PADK;

    int le0 = l * 2, le1 = l * 2 + 1;
    bool src_side = blockIdx.x < NBS;
    int bx = src_side ? blockIdx.x : blockIdx.x - NBS;
    const __half* X = src_side ? g_xsh : g_xth;
    int N = src_side ? N_SRC : N_TGT;
    int sec = blockIdx.y;                      // 0..2
    int slot_beg = sec * 4;
    int slot_end = (sec == 2) ? 13 : slot_beg + 4;

    int t = threadIdx.x;
    int rowbase = bx * 128;

    // stage A once (fp16)
    const uint4* xh4 = (const uint4*)X;
    uint4 z4 = make_uint4(0u, 0u, 0u, 0u);
    #pragma unroll
    for (int i = 0; i < 4; i++) {
        int idx = t + i * 256;
        int r = idx >> 3, c = idx & 7;
        int gr = rowbase + r;
        uint4 vh = z4;
        if (gr < N) vh = xh4[(size_t)gr * 8 + c];
        *(uint4*)(Ah + r * PADK + c * 8) = vh;
    }

    int lane = t & 31, warp = t >> 5;
    int wr = warp >> 1, wc = warp & 1;
    int lrow = lane & 7, lsel = lane >> 3;
    unsigned ah_u = su32(Ah), bh_u = su32(Bh), bl_u = su32(Bl);

    for (int slot = slot_beg; slot < slot_end; slot++) {
        int g = slot >> 2, lcb = slot & 3;     // slot 12 -> g=3, lcb=0
        int woff; const float* bias; __half* outh = 0; float* outf = 0;
        if (src_side) {
            if (g == 0)      { woff = le0 * WSECT + 256 * 64; bias = bk + le0 * 256; outh = g_k_st; }
            else if (g == 1) { woff = le0 * WSECT + 512 * 64; bias = bv + le0 * 256; outh = g_v_st; }
            else if (g == 2) { woff = le1 * WSECT;            bias = bq + le1 * 256; outh = g_q_ts; }
            else             { woff = le1 * WSECT + 768 * 64; bias = bs + le1 * 64;
                               outf = l ? g_xs_a : g_xs_b; }
        } else {
            if (g == 0)      { woff = le0 * WSECT;            bias = bq + le0 * 256; outh = g_q_st; }
            else if (g == 1) { woff = le1 * WSECT + 256 * 64; bias = bk + le1 * 256; outh = g_k_ts; }
            else if (g == 2) { woff = le1 * WSECT + 512 * 64; bias = bv + le1 * 256; outh = g_v_ts; }
            else             { woff = le0 * WSECT + 768 * 64; bias = bs + le0 * 64;
                               outf = l ? g_xt_a : g_xt_b; }
        }
        woff += lcb * 64 * 64;

        if (slot != slot_beg) __syncthreads();     // prev slot's B readers done
        const uint4* wh4 = (const uint4*)(g_wth + woff);
        const uint4* wl4 = (const uint4*)(g_wtl + woff);
        #pragma unroll
        for (int i = 0; i < 2; i++) {
            int idx = t + i * 256;
            int n = idx >> 3, c = idx & 7;
            *(uint4*)(Bh + n * PADK + c * 8) = wh4[n * 8 + c];
            *(uint4*)(Bl + n * PADK + c * 8) = wl4[n * 8 + c];
        }
        __syncthreads();                           // A (first slot) + B staged

        float acc[2][4][4];
        #pragma unroll
        for (int mt = 0; mt < 2; mt++)
            #pragma unroll
            for (int nt = 0; nt < 4; nt++)
                #pragma unroll
                for (int r = 0; r < 4; r++) acc[mt][nt][r] = 0.0f;

        #pragma unroll
        for (int kc = 0; kc < 4; kc++) {
            int k0 = kc * 16;
            unsigned ah[2][4], bh[2][4], bl[2][4];
            #pragma unroll
            for (int mt = 0; mt < 2; mt++) {
                int row = wr * 32 + mt * 16 + (lsel & 1) * 8 + lrow;
                int koff = k0 + (lsel >> 1) * 8;
                unsigned boff = (unsigned)(row * PADK + koff) * 2u;
                ldsm4(ah[mt][0], ah[mt][1], ah[mt][2], ah[mt][3], ah_u + boff);
            }
            #pragma unroll
            for (int nt2 = 0; nt2 < 2; nt2++) {
                int n = wc * 32 + nt2 * 16 + (lsel >> 1) * 8 + lrow;
                int koff = k0 + (lsel & 1) * 8;
                unsigned boff = (unsigned)(n * PADK + koff) * 2u;
                ldsm4(bh[nt2][0], bh[nt2][1], bh[nt2][2], bh[nt2][3], bh_u + boff);
                ldsm4(bl[nt2][0], bl[nt2][1], bl[nt2][2], bl[nt2][3], bl_u + boff);
            }
            #pragma unroll
            for (int mt = 0; mt < 2; mt++)
                #pragma unroll
                for (int nt = 0; nt < 4; nt++) {
                    int gg = nt >> 1, hf = (nt & 1) * 2;
                    mma16816h(acc[mt][nt], ah[mt], bh[gg][hf], bh[gg][hf + 1]);
                    mma16816h(acc[mt][nt], ah[mt], bl[gg][hf], bl[gg][hf + 1]);
                }
        }

        #pragma unroll
        for (int mt = 0; mt < 2; mt++) {
            int ra = rowbase + wr * 32 + mt * 16 + (lane >> 2);
            int rb = ra + 8;
            #pragma unroll
            for (int nt = 0; nt < 4; nt++) {
                int col = lcb * 64 + wc * 32 + nt * 8 + (lane & 3) * 2;
                float2 bv2 = *(const float2*)(bias + col);
                if (outh) {
                    if (ra < N)
                        *(__half2*)(outh + (size_t)ra * 256 + col) =
                            __floats2half2_rn(acc[mt][nt][0] + bv2.x, acc[mt][nt][1] + bv2.y);
                    if (rb < N)
                        *(__half2*)(outh + (size_t)rb * 256 + col) =
                            __floats2half2_rn(acc[mt][nt][2] + bv2.x, acc[mt][nt][3] + bv2.y);
                } else {
                    if (ra < N)
                        *(float2*)(outf + (size_t)ra * 64 + col) =
                            make_float2(acc[mt][nt][0] + bv2.x, acc[mt][nt][1] + bv2.y);
                    if (rb < N)
                        *(float2*)(outf + (size_t)rb * 64 + col) =
                            make_float2(acc[mt][nt][2] + bv2.x, acc[mt][nt][3] + bv2.y);
                }
            }
        }
    }
}

// ---------------- fused score+exp+denom: both directions ----------------
__global__ void scoreexp2(const int* __restrict__ e_st, const int* __restrict__ e_ts) {
    int gw = (blockIdx.x * blockDim.x + threadIdx.x) >> 5;
    if (gw >= 2 * N_E) return;
    int lane = threadIdx.x & 31;
    bool st = gw < N_E;
    int e = st ? gw : gw - N_E;
    const int* eidx = st ? e_st : e_ts;
    const __half* q = st ? g_q_st : g_q_ts;
    const __half* k = st ? g_k_st : g_k_ts;
    float* score = st ? g_sc_st : g_sc_ts;
    float* denom = st ? g_d_st : g_d_ts;

    int s = eidx[e], d = eidx[N_E + e];
    int h = lane >> 3, sub = lane & 7;
    uint4 qa = *(const uint4*)(q + (size_t)d * QKDIM + h * HDIM + sub * 8);
    uint4 ka = *(const uint4*)(k + (size_t)s * QKDIM + h * HDIM + sub * 8);
    float dot = dot8h(qa, ka);
    dot += __shfl_down_sync(0xffffffffu, dot, 4, 8);
    dot += __shfl_down_sync(0xffffffffu, dot, 2, 8);
    dot += __shfl_down_sync(0xffffffffu, dot, 1, 8);
    if (sub == 0) {
        float ex = __expf(dot * 0.125f);
        score[(size_t)e * NHEADS + h] = ex;
        atomicAdd(&denom[(size_t)d * NHEADS + h], ex);
    }
}

// ---------------- aggregation: both directions ----------------
__global__ void agg2(const int* __restrict__ e_st, const int* __restrict__ e_ts, int l) {
    int gw = (blockIdx.x * blockDim.x + threadIdx.x) >> 5;
    if (gw >= 2 * N_E) return;
    int lane = threadIdx.x & 31;
    bool st = gw < N_E;
    int e = st ? gw : gw - N_E;
    const int* eidx = st ? e_st : e_ts;
    const float* sc = st ? g_sc_st : g_sc_ts;
    const float* den = st ? g_d_st : g_d_ts;
    const __half* v = st ? g_v_st : g_v_ts;
    float* out = st ? (l ? g_xt_a : g_xt_b) : (l ? g_xs_a : g_xs_b);

    int s = eidx[e], d = eidx[N_E + e];
    size_t eb = (size_t)e * NHEADS, db = (size_t)d * NHEADS;
    float a0 = sc[eb + 0] / den[db + 0];
    float a1 = sc[eb + 1] / den[db + 1];
    float a2 = sc[eb + 2] / den[db + 2];
    float a3 = sc[eb + 3] / den[db + 3];
    const __half2* vp = (const __half2*)(v + (size_t)s * QKDIM);
    float2 v0 = __half22float2(vp[lane]);
    float2 v1 = __half22float2(vp[32 + lane]);
    float2 v2 = __half22float2(vp[64 + lane]);
    float2 v3 = __half22float2(vp[96 + lane]);
    float ax = 0.25f * (a0 * v0.x + a1 * v1.x + a2 * v2.x + a3 * v3.x);
    float ay = 0.25f * (a0 * v0.y + a1 * v1.y + a2 * v2.y + a3 * v3.y);
    atomicAdd(&out[(size_t)d * HDIM + lane * 2 + 0], ax);
    atomicAdd(&out[(size_t)d * HDIM + lane * 2 + 1], ay);
}

// ---------------- classifier ----------------
__global__ void pred_kernel(const int* __restrict__ l0, const int* __restrict__ l1,
                            const float* __restrict__ xs, const float* __restrict__ xt,
                            float* __restrict__ out, int n) {
    int gid = blockIdx.x * blockDim.x + threadIdx.x;
    int pair = gid >> 3, sub = gid & 7;
    if (pair >= n) return;
    int a = l0[pair], b = l1[pair];
    const float4* xa = (const float4*)(xs + (size_t)a * HDIM);
    const float4* xb = (const float4*)(xt + (size_t)b * HDIM);
    float4 p0 = xa[sub * 2], p1 = xa[sub * 2 + 1];
    float4 q0 = xb[sub * 2], q1 = xb[sub * 2 + 1];
    float dot = p0.x * q0.x + p0.y * q0.y + p0.z * q0.z + p0.w * q0.w
              + p1.x * q1.x + p1.y * q1.y + p1.z * q1.z + p1.w * q1.w;
    dot += __shfl_down_sync(0xffffffffu, dot, 4, 8);
    dot += __shfl_down_sync(0xffffffffu, dot, 2, 8);
    dot += __shfl_down_sync(0xffffffffu, dot, 1, 8);
    if (sub == 0) out[pair] = dot;
}

// ---------------- launch ----------------
extern "C" void kernel_launch(void* const* d_in, const int* in_sizes, int n_in,
                              void* d_out, int out_size) {
    const float* src_emb = (const float*)d_in[0];
    const float* tgt_emb = (const float*)d_in[1];
    const float* Wq = (const float*)d_in[2];
    const float* bq = (const float*)d_in[3];
    const float* Wk = (const float*)d_in[4];
    const float* bk = (const float*)d_in[5];
    const float* Wv = (const float*)d_in[6];
    const float* bv = (const float*)d_in[7];
    const float* Ws = (const float*)d_in[8];
    const float* bs = (const float*)d_in[9];
    const int* nid_s = (const int*)d_in[10];
    const int* nid_t = (const int*)d_in[11];
    const int* e_st  = (const int*)d_in[12];
    const int* e_ts  = (const int*)d_in[13];
    const int* lbl   = (const int*)d_in[14];
    float* out = (float*)d_out;

    float *xs_a, *xt_a, *d_st, *d_ts;
    cudaGetSymbolAddress((void**)&xs_a, g_xs_a);
    cudaGetSymbolAddress((void**)&xt_a, g_xt_a);
    cudaGetSymbolAddress((void**)&d_st, g_d_st);
    cudaGetSymbolAddress((void**)&d_ts, g_d_ts);

    const int SMEM = (128 * PADK + 64 * PADK * 2) * 2;  // 36864 B
    cudaFuncSetAttribute(proj_all, cudaFuncAttributeMaxDynamicSharedMemorySize, SMEM);

    int nz0 = (N_TGT + N_SRC) * NHEADS;
    int nx = (N_SRC + N_TGT) * HDIM;
    zero2_kernel<<<(nz0 + 255) / 256, 256>>>(d_st, N_TGT * NHEADS, d_ts, N_SRC * NHEADS);
    gather_h2<<<(nx + 255) / 256, 256>>>(src_emb, tgt_emb, nid_s, nid_t);
    split_w<<<(4 * WSECT + 255) / 256, 256>>>(Wq, Wk, Wv, Ws);

    int eb2 = (2 * N_E * 32 + 255) / 256;  // one warp per edge, both directions

    for (int l = 0; l < 2; l++) {
        if (l) {
            relu_h2<<<(nx + 255) / 256, 256>>>();
            zero2_kernel<<<(nz0 + 255) / 256, 256>>>(d_st, N_TGT * NHEADS, d_ts, N_SRC * NHEADS);
        }

        dim3 gall(NBS + NBT, 3);
        proj_all<<<gall, 256, SMEM>>>(l, bq, bk, bv, bs);

        scoreexp2<<<eb2, 256>>>(e_st, e_ts);
        agg2<<<eb2, 256>>>(e_st, e_ts, l);
    }

    pred_kernel<<<(N_LBL * 8 + 255) / 256, 256>>>(lbl, lbl + N_LBL, xs_a, xt_a, out, N_LBL);
}

// round 14
// speedup vs baseline: 1.2275x; 1.2275x over previous
#include <cuda_runtime.h>
#include <cuda_fp16.h>

#define HDIM   64
#define NHEADS 4
#define QKDIM  256           // NHEADS * HDIM
#define N_SRC  50000
#define N_TGT  10000
#define N_E    250000
#define N_LBL  200000

#define PADK   72            // smem row stride in fp16 (144B): ldmatrix conflict-free
#define WSECT  (832 * 64)    // per (layer,edge_type) transposed weight block (elements)

// ---------------- scratch (static device memory; no allocations) ----------------
__device__ float g_xs_a[N_SRC * HDIM];
__device__ float g_xs_b[N_SRC * HDIM];
__device__ float g_xt_a[N_TGT * HDIM];
__device__ float g_xt_b[N_TGT * HDIM];

// fp16 edge operands
__device__ __align__(16) __half g_q_st[N_TGT * QKDIM];
__device__ __align__(16) __half g_k_ts[N_TGT * QKDIM];
__device__ __align__(16) __half g_v_ts[N_TGT * QKDIM];
__device__ __align__(16) __half g_q_ts[N_SRC * QKDIM];
__device__ __align__(16) __half g_k_st[N_SRC * QKDIM];
__device__ __align__(16) __half g_v_st[N_SRC * QKDIM];

__device__ float g_sc_st[N_E * NHEADS];
__device__ float g_sc_ts[N_E * NHEADS];
__device__ float g_d_st[N_TGT * NHEADS];
__device__ float g_d_ts[N_SRC * NHEADS];

// A operand: fp16. B: split-fp16 (hi + residual).
__device__ __align__(16) __half g_xsh[N_SRC * HDIM];
__device__ __align__(16) __half g_xth[N_TGT * HDIM];
__device__ __align__(16) __half g_wth[4 * WSECT];
__device__ __align__(16) __half g_wtl[4 * WSECT];

// ---------------- helpers ----------------
__device__ __forceinline__ void split2h(float v, __half& h, __half& l) {
    h = __float2half_rn(v);
    l = __float2half_rn(v - __half2float(h));
}
__device__ __forceinline__ unsigned su32(const void* p) {
    unsigned a;
    asm("{ .reg .u64 t; cvta.to.shared.u64 t, %1; cvt.u32.u64 %0, t; }" : "=r"(a) : "l"(p));
    return a;
}
__device__ __forceinline__ void ldsm4(unsigned& r0, unsigned& r1, unsigned& r2, unsigned& r3,
                                      unsigned addr) {
    asm volatile("ldmatrix.sync.aligned.m8n8.x4.shared.b16 {%0,%1,%2,%3}, [%4];"
                 : "=r"(r0), "=r"(r1), "=r"(r2), "=r"(r3) : "r"(addr));
}
__device__ __forceinline__ void mma16816h(float* d, const unsigned* a, unsigned b0, unsigned b1) {
    asm volatile("mma.sync.aligned.m16n8k16.row.col.f32.f16.f16.f32 "
                 "{%0,%1,%2,%3}, {%4,%5,%6,%7}, {%8,%9}, {%0,%1,%2,%3};"
                 : "+f"(d[0]), "+f"(d[1]), "+f"(d[2]), "+f"(d[3])
                 : "r"(a[0]), "r"(a[1]), "r"(a[2]), "r"(a[3]), "r"(b0), "r"(b1));
}
__device__ __forceinline__ float dot8h(uint4 qa, uint4 ka) {
    const __half2* qh = (const __half2*)&qa;
    const __half2* kh = (const __half2*)&ka;
    float dot = 0.0f;
    #pragma unroll
    for (int i = 0; i < 4; i++) {
        float2 a = __half22float2(qh[i]);
        float2 b = __half22float2(kh[i]);
        dot += a.x * b.x + a.y * b.y;
    }
    return dot;
}
// vector reduction add (sm_90+): one 16B atomic instead of 4 scalar ones
__device__ __forceinline__ void red_add_v4(float* p, float a, float b, float c, float d) {
    asm volatile("red.global.add.v4.f32 [%0], {%1, %2, %3, %4};"
                 :: "l"(p), "f"(a), "f"(b), "f"(c), "f"(d) : "memory");
}

// ---------------- small kernels ----------------
__global__ void zero2_kernel(float* __restrict__ a, int na, float* __restrict__ b, int nb) {
    int i = blockIdx.x * blockDim.x + threadIdx.x;
    if (i < na) { a[i] = 0.0f; return; }
    i -= na;
    if (i < nb) b[i] = 0.0f;
}

__global__ void gather_h2(const float* __restrict__ semb, const float* __restrict__ temb,
                          const int* __restrict__ sid, const int* __restrict__ tid) {
    int i = blockIdx.x * blockDim.x + threadIdx.x;
    if (i < N_SRC * HDIM) {
        int row = i >> 6, d = i & 63;
        g_xsh[i] = __float2half_rn(semb[(size_t)sid[row] * HDIM + d]);
    } else if (i < (N_SRC + N_TGT) * HDIM) {
        int j = i - N_SRC * HDIM;
        int row = j >> 6, d = j & 63;
        g_xth[j] = __float2half_rn(temb[(size_t)tid[row] * HDIM + d]);
    }
}

__global__ void relu_h2() {
    int i = blockIdx.x * blockDim.x + threadIdx.x;
    if (i < N_SRC * HDIM) {
        g_xsh[i] = __float2half_rn(fmaxf(g_xs_b[i], 0.0f));
    } else if (i < (N_SRC + N_TGT) * HDIM) {
        int j = i - N_SRC * HDIM;
        g_xth[j] = __float2half_rn(fmaxf(g_xt_b[j], 0.0f));
    }
}

__global__ void split_w(const float* __restrict__ Wq, const float* __restrict__ Wk,
                        const float* __restrict__ Wv, const float* __restrict__ Ws) {
    int i = blockIdx.x * blockDim.x + threadIdx.x;
    if (i >= 4 * WSECT) return;
    int le = i / WSECT, rem = i % WSECT;
    int n = rem >> 6, k = rem & 63;
    float v;
    if (n < 256)      v = Wq[(size_t)le * 64 * 256 + k * 256 + n];
    else if (n < 512) v = Wk[(size_t)le * 64 * 256 + k * 256 + (n - 256)];
    else if (n < 768) v = Wv[(size_t)le * 64 * 256 + k * 256 + (n - 512)];
    else              v = Ws[(size_t)le * 64 * 64 + k * 64 + (n - 768)];
    split2h(v, g_wth[i], g_wtl[i]);
}

// ---------------- tensor-core projection GEMM (exact R11 champion) ------
__global__ void __launch_bounds__(256) proj_mma(
    const __half* __restrict__ Xh, int N,
    int off0, int off1, int off2, int off3,
    const float* __restrict__ b0, const float* __restrict__ b1,
    const float* __restrict__ b2, const float* __restrict__ b3,
    __half* __restrict__ o0, __half* __restrict__ o1,
    __half* __restrict__ o2, float* __restrict__ o3) {
    extern __shared__ __half sm[];
    __half* Ah = sm;                           // [128][PADK]
    __half* Bh = Ah + 128 * PADK;              // [64][PADK]
    __half* Bl = Bh + 64 * PADK;

    int sec = blockIdx.y;                      // 0..3
    int woff_base, ncb; const float* bias; __half* outh = 0; float* outf = 0;
    if (sec == 0)      { woff_base = off0; bias = b0; outh = o0; ncb = 4; }
    else if (sec == 1) { woff_base = off1; bias = b1; outh = o1; ncb = 4; }
    else if (sec == 2) { woff_base = off2; bias = b2; outh = o2; ncb = 4; }
    else               { woff_base = off3; bias = b3; outf = o3; ncb = 1; }

    int t = threadIdx.x;
    int rowbase = blockIdx.x * 128;

    const uint4* xh4 = (const uint4*)Xh;
    uint4 z4 = make_uint4(0u, 0u, 0u, 0u);
    #pragma unroll
    for (int i = 0; i < 4; i++) {
        int idx = t + i * 256;
        int r = idx >> 3, c = idx & 7;
        int gr = rowbase + r;
        uint4 vh = z4;
        if (gr < N) vh = xh4[(size_t)gr * 8 + c];
        *(uint4*)(Ah + r * PADK + c * 8) = vh;
    }

    int lane = t & 31, warp = t >> 5;
    int wr = warp >> 1, wc = warp & 1;
    int lrow = lane & 7, lsel = lane >> 3;
    unsigned ah_u = su32(Ah), bh_u = su32(Bh), bl_u = su32(Bl);

    for (int lcb = 0; lcb < ncb; lcb++) {
        if (lcb) __syncthreads();
        int woff = woff_base + lcb * 64 * 64;
        const uint4* wh4 = (const uint4*)(g_wth + woff);
        const uint4* wl4 = (const uint4*)(g_wtl + woff);
        #pragma unroll
        for (int i = 0; i < 2; i++) {
            int idx = t + i * 256;
            int n = idx >> 3, c = idx & 7;
            *(uint4*)(Bh + n * PADK + c * 8) = wh4[n * 8 + c];
            *(uint4*)(Bl + n * PADK + c * 8) = wl4[n * 8 + c];
        }
        __syncthreads();

        float acc[2][4][4];
        #pragma unroll
        for (int mt = 0; mt < 2; mt++)
            #pragma unroll
            for (int nt = 0; nt < 4; nt++)
                #pragma unroll
                for (int r = 0; r < 4; r++) acc[mt][nt][r] = 0.0f;

        #pragma unroll
        for (int kc = 0; kc < 4; kc++) {
            int k0 = kc * 16;
            unsigned ah[2][4], bh[2][4], bl[2][4];
            #pragma unroll
            for (int mt = 0; mt < 2; mt++) {
                int row = wr * 32 + mt * 16 + (lsel & 1) * 8 + lrow;
                int koff = k0 + (lsel >> 1) * 8;
                unsigned boff = (unsigned)(row * PADK + koff) * 2u;
                ldsm4(ah[mt][0], ah[mt][1], ah[mt][2], ah[mt][3], ah_u + boff);
            }
            #pragma unroll
            for (int nt2 = 0; nt2 < 2; nt2++) {
                int n = wc * 32 + nt2 * 16 + (lsel >> 1) * 8 + lrow;
                int koff = k0 + (lsel & 1) * 8;
                unsigned boff = (unsigned)(n * PADK + koff) * 2u;
                ldsm4(bh[nt2][0], bh[nt2][1], bh[nt2][2], bh[nt2][3], bh_u + boff);
                ldsm4(bl[nt2][0], bl[nt2][1], bl[nt2][2], bl[nt2][3], bl_u + boff);
            }
            #pragma unroll
            for (int mt = 0; mt < 2; mt++)
                #pragma unroll
                for (int nt = 0; nt < 4; nt++) {
                    int g = nt >> 1, hf = (nt & 1) * 2;
                    mma16816h(acc[mt][nt], ah[mt], bh[g][hf], bh[g][hf + 1]);
                    mma16816h(acc[mt][nt], ah[mt], bl[g][hf], bl[g][hf + 1]);
                }
        }

        #pragma unroll
        for (int mt = 0; mt < 2; mt++) {
            int ra = rowbase + wr * 32 + mt * 16 + (lane >> 2);
            int rb = ra + 8;
            #pragma unroll
            for (int nt = 0; nt < 4; nt++) {
                int col = lcb * 64 + wc * 32 + nt * 8 + (lane & 3) * 2;
                float2 bv = *(const float2*)(bias + col);
                if (sec < 3) {
                    if (ra < N)
                        *(__half2*)(outh + (size_t)ra * 256 + col) =
                            __floats2half2_rn(acc[mt][nt][0] + bv.x, acc[mt][nt][1] + bv.y);
                    if (rb < N)
                        *(__half2*)(outh + (size_t)rb * 256 + col) =
                            __floats2half2_rn(acc[mt][nt][2] + bv.x, acc[mt][nt][3] + bv.y);
                } else {
                    if (ra < N)
                        *(float2*)(outf + (size_t)ra * 64 + col) =
                            make_float2(acc[mt][nt][0] + bv.x, acc[mt][nt][1] + bv.y);
                    if (rb < N)
                        *(float2*)(outf + (size_t)rb * 64 + col) =
                            make_float2(acc[mt][nt][2] + bv.x, acc[mt][nt][3] + bv.y);
                }
            }
        }
    }
}

// ---------------- fused score+exp+denom pass (R11) ----------------
__global__ void scoreexp_kernel(const int* __restrict__ esrc, const int* __restrict__ edst,
                                const __half* __restrict__ q, const __half* __restrict__ k,
                                float* __restrict__ score, float* __restrict__ denom,
                                int nedge) {
    int warp = (blockIdx.x * blockDim.x + threadIdx.x) >> 5;
    if (warp >= nedge) return;
    int lane = threadIdx.x & 31;
    int s = esrc[warp], d = edst[warp];
    int h = lane >> 3, sub = lane & 7;
    uint4 qa = *(const uint4*)(q + (size_t)d * QKDIM + h * HDIM + sub * 8);
    uint4 ka = *(const uint4*)(k + (size_t)s * QKDIM + h * HDIM + sub * 8);
    float dot = dot8h(qa, ka);
    dot += __shfl_down_sync(0xffffffffu, dot, 4, 8);
    dot += __shfl_down_sync(0xffffffffu, dot, 2, 8);
    dot += __shfl_down_sync(0xffffffffu, dot, 1, 8);
    if (sub == 0) {
        float ex = __expf(dot * 0.125f);
        score[(size_t)warp * NHEADS + h] = ex;
        atomicAdd(&denom[(size_t)d * NHEADS + h], ex);
    }
}

// ---------------- aggregation: 2 edges per warp, v4 vector atomics ----------------
// 16 lanes per edge; lane owns 4 consecutive output floats -> one red.v4 per lane.
__global__ void agg_kernel(const int* __restrict__ esrc, const int* __restrict__ edst,
                           const float* __restrict__ sc, const float* __restrict__ den,
                           const __half* __restrict__ v, float* __restrict__ out, int nedge) {
    int gw = (blockIdx.x * blockDim.x + threadIdx.x) >> 5;
    int lane = threadIdx.x & 31;
    int e = gw * 2 + (lane >> 4);
    if (e >= nedge) return;
    int li = lane & 15;                        // output floats [li*4, li*4+4)

    int s = esrc[e], d = edst[e];
    float4 scv = *(const float4*)(sc + (size_t)e * NHEADS);
    float4 dnv = *(const float4*)(den + (size_t)d * NHEADS);
    float a0 = 0.25f * scv.x / dnv.x;
    float a1 = 0.25f * scv.y / dnv.y;
    float a2 = 0.25f * scv.z / dnv.z;
    float a3 = 0.25f * scv.w / dnv.w;

    // v[s, h*64 + li*4 .. +4): 4 halves = 8B per head
    const __half* vb = v + (size_t)s * QKDIM + li * 4;
    uint2 r0 = *(const uint2*)(vb);
    uint2 r1 = *(const uint2*)(vb + 64);
    uint2 r2 = *(const uint2*)(vb + 128);
    uint2 r3 = *(const uint2*)(vb + 192);
    const __half2* h0 = (const __half2*)&r0;
    const __half2* h1 = (const __half2*)&r1;
    const __half2* h2 = (const __half2*)&r2;
    const __half2* h3 = (const __half2*)&r3;
    float2 v0a = __half22float2(h0[0]), v0b = __half22float2(h0[1]);
    float2 v1a = __half22float2(h1[0]), v1b = __half22float2(h1[1]);
    float2 v2a = __half22float2(h2[0]), v2b = __half22float2(h2[1]);
    float2 v3a = __half22float2(h3[0]), v3b = __half22float2(h3[1]);

    float o0 = a0 * v0a.x + a1 * v1a.x + a2 * v2a.x + a3 * v3a.x;
    float o1 = a0 * v0a.y + a1 * v1a.y + a2 * v2a.y + a3 * v3a.y;
    float o2 = a0 * v0b.x + a1 * v1b.x + a2 * v2b.x + a3 * v3b.x;
    float o3 = a0 * v0b.y + a1 * v1b.y + a2 * v2b.y + a3 * v3b.y;

    red_add_v4(out + (size_t)d * HDIM + li * 4, o0, o1, o2, o3);
}

// ---------------- classifier ----------------
__global__ void pred_kernel(const int* __restrict__ l0, const int* __restrict__ l1,
                            const float* __restrict__ xs, const float* __restrict__ xt,
                            float* __restrict__ out, int n) {
    int gid = blockIdx.x * blockDim.x + threadIdx.x;
    int pair = gid >> 3, sub = gid & 7;
    if (pair >= n) return;
    int a = l0[pair], b = l1[pair];
    const float4* xa = (const float4*)(xs + (size_t)a * HDIM);
    const float4* xb = (const float4*)(xt + (size_t)b * HDIM);
    float4 p0 = xa[sub * 2], p1 = xa[sub * 2 + 1];
    float4 q0 = xb[sub * 2], q1 = xb[sub * 2 + 1];
    float dot = p0.x * q0.x + p0.y * q0.y + p0.z * q0.z + p0.w * q0.w
              + p1.x * q1.x + p1.y * q1.y + p1.z * q1.z + p1.w * q1.w;
    dot += __shfl_down_sync(0xffffffffu, dot, 4, 8);
    dot += __shfl_down_sync(0xffffffffu, dot, 2, 8);
    dot += __shfl_down_sync(0xffffffffu, dot, 1, 8);
    if (sub == 0) out[pair] = dot;
}

// ---------------- launch ----------------
extern "C" void kernel_launch(void* const* d_in, const int* in_sizes, int n_in,
                              void* d_out, int out_size) {
    const float* src_emb = (const float*)d_in[0];
    const float* tgt_emb = (const float*)d_in[1];
    const float* Wq = (const float*)d_in[2];
    const float* bq = (const float*)d_in[3];
    const float* Wk = (const float*)d_in[4];
    const float* bk = (const float*)d_in[5];
    const float* Wv = (const float*)d_in[6];
    const float* bv = (const float*)d_in[7];
    const float* Ws = (const float*)d_in[8];
    const float* bs = (const float*)d_in[9];
    const int* nid_s = (const int*)d_in[10];
    const int* nid_t = (const int*)d_in[11];
    const int* e_st  = (const int*)d_in[12];
    const int* e_ts  = (const int*)d_in[13];
    const int* lbl   = (const int*)d_in[14];
    float* out = (float*)d_out;

    float *xs_a, *xs_b, *xt_a, *xt_b, *sc_st, *sc_ts, *d_st, *d_ts;
    __half *q_st, *k_ts, *v_ts, *q_ts, *k_st, *v_st, *xsh, *xth;
    cudaGetSymbolAddress((void**)&xs_a, g_xs_a);
    cudaGetSymbolAddress((void**)&xs_b, g_xs_b);
    cudaGetSymbolAddress((void**)&xt_a, g_xt_a);
    cudaGetSymbolAddress((void**)&xt_b, g_xt_b);
    cudaGetSymbolAddress((void**)&q_st, g_q_st);
    cudaGetSymbolAddress((void**)&k_ts, g_k_ts);
    cudaGetSymbolAddress((void**)&v_ts, g_v_ts);
    cudaGetSymbolAddress((void**)&q_ts, g_q_ts);
    cudaGetSymbolAddress((void**)&k_st, g_k_st);
    cudaGetSymbolAddress((void**)&v_st, g_v_st);
    cudaGetSymbolAddress((void**)&sc_st, g_sc_st);
    cudaGetSymbolAddress((void**)&sc_ts, g_sc_ts);
    cudaGetSymbolAddress((void**)&d_st, g_d_st);
    cudaGetSymbolAddress((void**)&d_ts, g_d_ts);
    cudaGetSymbolAddress((void**)&xsh, g_xsh);
    cudaGetSymbolAddress((void**)&xth, g_xth);

    const int SMEM = (128 * PADK + 64 * PADK * 2) * 2;  // 36864 B
    cudaFuncSetAttribute(proj_mma, cudaFuncAttributeMaxDynamicSharedMemorySize, SMEM);

    int nz0 = (N_TGT + N_SRC) * NHEADS;
    int nx = (N_SRC + N_TGT) * HDIM;
    zero2_kernel<<<(nz0 + 255) / 256, 256>>>(d_st, N_TGT * NHEADS, d_ts, N_SRC * NHEADS);
    gather_h2<<<(nx + 255) / 256, 256>>>(src_emb, tgt_emb, nid_s, nid_t);
    split_w<<<(4 * WSECT + 255) / 256, 256>>>(Wq, Wk, Wv, Ws);

    int sb = (N_E * 32 + 255) / 256;              // one warp per edge (scoreexp)
    int ab = (((N_E + 1) / 2) * 32 + 255) / 256;  // two edges per warp (agg)

    for (int l = 0; l < 2; l++) {
        float* out_s = l ? xs_a : xs_b;
        float* out_t = l ? xt_a : xt_b;
        if (l) {
            relu_h2<<<(nx + 255) / 256, 256>>>();
            zero2_kernel<<<(nz0 + 255) / 256, 256>>>(d_st, N_TGT * NHEADS, d_ts, N_SRC * NHEADS);
        }

        int le0 = l * 2 + 0, le1 = l * 2 + 1;
        dim3 gs((N_SRC + 127) / 128, 4), gt((N_TGT + 127) / 128, 4);
        // src-side: k_st(Wk l,0), v_st(Wv l,0), q_ts(Wq l,1), skip(Ws l,1)
        proj_mma<<<gs, 256, SMEM>>>(xsh, N_SRC,
            le0 * WSECT + 256 * 64, le0 * WSECT + 512 * 64,
            le1 * WSECT + 0,        le1 * WSECT + 768 * 64,
            bk + le0 * 256, bv + le0 * 256, bq + le1 * 256, bs + le1 * 64,
            k_st, v_st, q_ts, out_s);
        // tgt-side: q_st(Wq l,0), k_ts(Wk l,1), v_ts(Wv l,1), skip(Ws l,0)
        proj_mma<<<gt, 256, SMEM>>>(xth, N_TGT,
            le0 * WSECT + 0,        le1 * WSECT + 256 * 64,
            le1 * WSECT + 512 * 64, le0 * WSECT + 768 * 64,
            bq + le0 * 256, bk + le1 * 256, bv + le1 * 256, bs + le0 * 64,
            q_st, k_ts, v_ts, out_t);

        scoreexp_kernel<<<sb, 256>>>(e_st, e_st + N_E, q_st, k_st, sc_st, d_st, N_E);
        scoreexp_kernel<<<sb, 256>>>(e_ts, e_ts + N_E, q_ts, k_ts, sc_ts, d_ts, N_E);

        agg_kernel<<<ab, 256>>>(e_st, e_st + N_E, sc_st, d_st, v_st, out_t, N_E);
        agg_kernel<<<ab, 256>>>(e_ts, e_ts + N_E, sc_ts, d_ts, v_ts, out_s, N_E);
    }

    pred_kernel<<<(N_LBL * 8 + 255) / 256, 256>>>(lbl, lbl + N_LBL, xs_a, xt_a, out, N_LBL);
}